// round 3
// baseline (speedup 1.0000x reference)
#include <cuda_runtime.h>
#include <cuda_bf16.h>

#define CH 32

// ---------------- device scratch (static: no allocation) ----------------
__device__ float g_kv[2 * CH * 64 * 64];          // trans_layer output [b][c][64*64]
__device__ float g_q [2 * CH * 4096];             // query field        [b][c][4096]
__device__ float g_k [2 * 3 * CH * 4096];         // key fields         [b][i][c][4096]
__device__ float g_scores[2 * CH * 24];           // normalized scores  [b][c][m], m=i*8+j
__device__ float g_V [2 * 3 * CH * 65536];        // value fields       [b][i][c][65536]
__device__ float g_pre[2 * CH * 65536];           // pre out-conv       [b][c][65536]

// ---------------- K1: 5x5 stride-4 conv (trans_layer) ----------------
// block = 256 thr (8 warps). lane = co. Each block: one 8x8 output tile of one batch.
// Warp w handles output row w of the tile (8 pixels).
__global__ void k1_trans(const float* __restrict__ cen,
                         const float* __restrict__ tw,
                         const float* __restrict__ tb) {
    int bt   = blockIdx.x;
    int b    = bt >> 6;
    int tile = bt & 63;
    int ty0  = (tile >> 3) << 3;
    int tx0  = (tile & 7) << 3;
    int lane = threadIdx.x & 31;
    int warp = threadIdx.x >> 5;

    __shared__ float s_in[4][33][33];   // input tile for 4 input channels
    __shared__ float s_w[4][25][32];    // weights [ci][k][co]

    float acc[8];
#pragma unroll
    for (int p = 0; p < 8; p++) acc[p] = 0.f;

    int iy0 = ty0 * 4 - 2, ix0 = tx0 * 4 - 2;

    for (int cc = 0; cc < 32; cc += 4) {
        __syncthreads();
        for (int idx = threadIdx.x; idx < 4 * 25 * 32; idx += 256) {
            int co = idx & 31;
            int k  = (idx >> 5) % 25;
            int ci = idx / (25 * 32);
            s_w[ci][k][co] = tw[(co * 32 + cc + ci) * 25 + k];
        }
        for (int idx = threadIdx.x; idx < 4 * 33 * 33; idx += 256) {
            int xx = idx % 33;
            int yy = (idx / 33) % 33;
            int ci = idx / (33 * 33);
            int gy = iy0 + yy, gx = ix0 + xx;
            float v = 0.f;
            if ((unsigned)gy < 256u && (unsigned)gx < 256u)
                v = cen[((b * CH + cc + ci) * 256 + gy) * 256 + gx];
            s_in[ci][yy][xx] = v;
        }
        __syncthreads();
#pragma unroll
        for (int ci = 0; ci < 4; ci++)
#pragma unroll
            for (int ky = 0; ky < 5; ky++)
#pragma unroll
                for (int kx = 0; kx < 5; kx++) {
                    float wv = s_w[ci][ky * 5 + kx][lane];
#pragma unroll
                    for (int p = 0; p < 8; p++)
                        acc[p] = fmaf(wv, s_in[ci][warp * 4 + ky][p * 4 + kx], acc[p]);
                }
    }
    float bias = tb[lane];
    int oy = ty0 + warp;
#pragma unroll
    for (int p = 0; p < 8; p++) {
        int ox = tx0 + p;
        g_kv[((b * CH + lane) * 64 + oy) * 64 + ox] = acc[p] + bias;
    }
}

// ---------------- K2a: Q and K_i 1x1 convs on kv_cen ----------------
// grid: (16 pixel-chunks, 4 variants [q,k0,k1,k2], 2 batches), 256 thr
__global__ void k2a_qk(const float* __restrict__ qW, const float* __restrict__ kW) {
    int b   = blockIdx.z;
    int var = blockIdx.y;
    int p   = blockIdx.x * 256 + threadIdx.x;

    __shared__ float s_w[32][32];  // [cc][c]
    const float* W = (var == 0) ? qW : (kW + (var - 1) * CH * CH);
    for (int idx = threadIdx.x; idx < 1024; idx += 256) {
        int c = idx >> 5, cc = idx & 31;
        s_w[cc][c] = W[c * 32 + cc];
    }
    __syncthreads();

    float acc[32];
#pragma unroll
    for (int c = 0; c < 32; c++) acc[c] = 0.f;
    for (int cc = 0; cc < 32; cc++) {
        float x = g_kv[(b * CH + cc) * 4096 + p];
#pragma unroll
        for (int c = 0; c < 32; c++)
            acc[c] = fmaf(s_w[cc][c], x, acc[c]);
    }
    float* dst = (var == 0) ? (g_q + b * CH * 4096)
                            : (g_k + ((b * 3 + (var - 1)) * CH) * 4096);
#pragma unroll
    for (int c = 0; c < 32; c++)
        dst[c * 4096 + p] = acc[c];
}

__device__ __forceinline__ float warpReduce(float v) {
#pragma unroll
    for (int o = 16; o > 0; o >>= 1) v += __shfl_down_sync(0xffffffffu, v, o);
    return v;
}

// ---------------- K2b: scores, one block per (b,c) ----------------
__global__ void k2b_scores() {
    int b = blockIdx.x >> 5;
    int c = blockIdx.x & 31;
    __shared__ float sQ[4096];
    __shared__ float sK[4096];
    __shared__ float s_red[8];
    __shared__ float s_skk[24], s_sqk[24];
    __shared__ float s_sqq;
    int tid = threadIdx.x;
    int lane = tid & 31, warp = tid >> 5;
    constexpr int DY[8] = {-1, -1, -1, 0, 1, 1, 1, 0};
    constexpr int DX[8] = {-1, 0, 1, 1, 1, 0, -1, -1};
    constexpr int SH[3] = {1, 2, 4};

    float qn = 0.f;
    for (int p = tid; p < 4096; p += 256) {
        float a = g_q[(b * CH + c) * 4096 + p];
        sQ[p] = a;
        qn = fmaf(a, a, qn);
    }
    qn = warpReduce(qn);
    if (lane == 0) s_red[warp] = qn;
    __syncthreads();
    if (tid == 0) {
        float s = 0.f;
        for (int w = 0; w < 8; w++) s += s_red[w];
        s_sqq = s;
    }

    for (int i = 0; i < 3; i++) {
        __syncthreads();
        for (int p = tid; p < 4096; p += 256)
            sK[p] = g_k[((b * 3 + i) * CH + c) * 4096 + p];
        __syncthreads();
        int d = SH[i];
        float skk[8], sqk[8];
#pragma unroll
        for (int j = 0; j < 8; j++) { skk[j] = 0.f; sqk[j] = 0.f; }
        for (int p = tid; p < 4096; p += 256) {
            int y = p >> 6, x = p & 63;
            float kc = sK[p];
            float qv = sQ[p];
#pragma unroll
            for (int j = 0; j < 8; j++) {
                int ny = y + DY[j] * d, nx = x + DX[j] * d;
                float nb = ((unsigned)ny < 64u && (unsigned)nx < 64u)
                               ? sK[ny * 64 + nx] : 0.f;
                float v = kc - nb;
                skk[j] = fmaf(v, v, skk[j]);
                sqk[j] = fmaf(qv, v, sqk[j]);
            }
        }
        for (int j = 0; j < 8; j++) {
            float r = warpReduce(skk[j]);
            __syncthreads();
            if (lane == 0) s_red[warp] = r;
            __syncthreads();
            if (tid == 0) {
                float s = 0.f;
                for (int w2 = 0; w2 < 8; w2++) s += s_red[w2];
                s_skk[i * 8 + j] = s;
            }
            r = warpReduce(sqk[j]);
            __syncthreads();
            if (lane == 0) s_red[warp] = r;
            __syncthreads();
            if (tid == 0) {
                float s = 0.f;
                for (int w2 = 0; w2 < 8; w2++) s += s_red[w2];
                s_sqk[i * 8 + j] = s;
            }
        }
    }
    __syncthreads();
    if (tid == 0) {
        float qd = fmaxf(sqrtf(s_sqq), 1e-12f);
        float sc[24];
        float ss = 0.f;
        for (int m = 0; m < 24; m++) {
            float kd = fmaxf(sqrtf(s_skk[m]), 1e-12f);
            sc[m] = s_sqk[m] / (qd * kd);
            ss = fmaf(sc[m], sc[m], ss);
        }
        float sn = fmaxf(sqrtf(ss), 1e-12f);
        for (int m = 0; m < 24; m++)
            g_scores[(b * CH + c) * 24 + m] = sc[m] / sn;
    }
}

// ---------------- K3: value fields V_i = value_W[i] * cen ----------------
// grid: (256 chunks, 3 shifts, 2 batches), 256 thr; thread = pixel, 32 acc
__global__ void k3_value(const float* __restrict__ cen, const float* __restrict__ vW) {
    int b = blockIdx.z, i = blockIdx.y;
    int p = blockIdx.x * 256 + threadIdx.x;
    __shared__ float s_w[32][32];  // [cc][c]
    for (int idx = threadIdx.x; idx < 1024; idx += 256) {
        int c = idx >> 5, cc = idx & 31;
        s_w[cc][c] = vW[(i * CH + c) * CH + cc];
    }
    __syncthreads();
    float acc[32];
#pragma unroll
    for (int c = 0; c < 32; c++) acc[c] = 0.f;
    for (int cc = 0; cc < 32; cc++) {
        float x = cen[(b * CH + cc) * 65536 + p];
#pragma unroll
        for (int c = 0; c < 32; c++)
            acc[c] = fmaf(s_w[cc][c], x, acc[c]);
    }
#pragma unroll
    for (int c = 0; c < 32; c++)
        g_V[((b * 3 + i) * CH + c) * 65536 + p] = acc[c];
}

// ---------------- K4: 27-tap stencil combine with scores ----------------
// grid: (256 chunks, 32 channels, 2 batches), 256 thr
__global__ void k4_combine() {
    int b = blockIdx.z, c = blockIdx.y;
    int p = blockIdx.x * 256 + threadIdx.x;
    __shared__ float s_s[24];
    if (threadIdx.x < 24) s_s[threadIdx.x] = g_scores[(b * CH + c) * 24 + threadIdx.x];
    __syncthreads();
    constexpr int DY[8] = {-1, -1, -1, 0, 1, 1, 1, 0};
    constexpr int DX[8] = {-1, 0, 1, 1, 1, 0, -1, -1};
    constexpr int SH[3] = {1, 2, 4};
    int y = p >> 8, x = p & 255;
    float out = 0.f;
#pragma unroll
    for (int i = 0; i < 3; i++) {
        const float* V = g_V + ((b * 3 + i) * CH + c) * 65536;
        float A = 0.f;
#pragma unroll
        for (int j = 0; j < 8; j++) A += s_s[i * 8 + j];
        out = fmaf(A, V[p], out);
        int d = SH[i];
#pragma unroll
        for (int j = 0; j < 8; j++) {
            int ny = y + DY[j] * d, nx = x + DX[j] * d;
            float nb = ((unsigned)ny < 256u && (unsigned)nx < 256u)
                           ? V[ny * 256 + nx] : 0.f;
            out = fmaf(-s_s[i * 8 + j], nb, out);
        }
    }
    g_pre[(b * CH + c) * 65536 + p] = out;
}

// ---------------- K5: out 1x1 conv + BN (folded) + ReLU ----------------
// grid: (256 chunks, 2 batches), 256 thr; thread = pixel, 32 acc
__global__ void k5_out(const float* __restrict__ oW,
                       const float* __restrict__ gm, const float* __restrict__ bt,
                       const float* __restrict__ mn, const float* __restrict__ vr,
                       float* __restrict__ out) {
    int b = blockIdx.y;
    int p = blockIdx.x * 256 + threadIdx.x;
    __shared__ float s_w[32][32];  // [c][co]
    __shared__ float s_g[32], s_b[32];
    for (int idx = threadIdx.x; idx < 1024; idx += 256) {
        int co = idx & 31, c = idx >> 5;
        s_w[c][co] = oW[co * 32 + c];
    }
    if (threadIdx.x < 32) {
        float inv = rsqrtf(vr[threadIdx.x] + 1e-5f);
        float g = gm[threadIdx.x] * inv;
        s_g[threadIdx.x] = g;
        s_b[threadIdx.x] = bt[threadIdx.x] - mn[threadIdx.x] * g;
    }
    __syncthreads();
    float acc[32];
#pragma unroll
    for (int co = 0; co < 32; co++) acc[co] = 0.f;
    for (int c = 0; c < 32; c++) {
        float x = g_pre[(b * CH + c) * 65536 + p];
#pragma unroll
        for (int co = 0; co < 32; co++)
            acc[co] = fmaf(s_w[c][co], x, acc[co]);
    }
#pragma unroll
    for (int co = 0; co < 32; co++)
        out[(b * CH + co) * 65536 + p] = fmaxf(fmaf(acc[co], s_g[co], s_b[co]), 0.f);
}

// ---------------- launch ----------------
extern "C" void kernel_launch(void* const* d_in, const int* in_sizes, int n_in,
                              void* d_out, int out_size) {
    const float* cen     = (const float*)d_in[0];
    const float* trans_W = (const float*)d_in[1];
    const float* trans_b = (const float*)d_in[2];
    const float* query_W = (const float*)d_in[3];
    const float* value_W = (const float*)d_in[4];
    const float* key_W   = (const float*)d_in[5];
    const float* out_W   = (const float*)d_in[6];
    const float* bn_g    = (const float*)d_in[7];
    const float* bn_b    = (const float*)d_in[8];
    const float* bn_m    = (const float*)d_in[9];
    const float* bn_v    = (const float*)d_in[10];
    float* out = (float*)d_out;

    k1_trans  <<<128, 256>>>(cen, trans_W, trans_b);
    k2a_qk    <<<dim3(16, 4, 2), 256>>>(query_W, key_W);
    k2b_scores<<<64, 256>>>();
    k3_value  <<<dim3(256, 3, 2), 256>>>(cen, value_W);
    k4_combine<<<dim3(256, 32, 2), 256>>>();
    k5_out    <<<dim3(256, 2), 256>>>(out_W, bn_g, bn_b, bn_m, bn_v, out);
}